// round 6
// baseline (speedup 1.0000x reference)
#include <cuda_runtime.h>
#include <cstddef>

// ---------------------------------------------------------------------------
// DiffJPEG: per 8x8 block  ->  D X D^T  ->  round(x/Q)*Q  ->  D^T X' D
// Input/Output: (32, 3, 512, 512) float32, contiguous.
//
// One thread per 8x8 block (most issue-efficient layout; lane-pair split
// regressed in R4/5 by inflating issued work). This round:
//  - full even/odd butterfly: 8-pt transform = 36 ops (even 4x4 has its own
//    symmetric/antisymmetric split)
//  - Q and 1/Q folded into phase-2 matvec immediates (constexpr products)
//  - __launch_bounds__(256,4): 64-reg target -> 4 CTAs/SM
// ---------------------------------------------------------------------------

__host__ __device__ constexpr float COS9(int m) {
    constexpr float t[9] = {
        1.0f,
        0.9807852804032304f,
        0.9238795325112868f,
        0.8314696123025452f,
        0.7071067811865476f,
        0.5555702330196022f,
        0.3826834323650898f,
        0.1950903220161283f,
        0.0f
    };
    return t[m];
}

__host__ __device__ constexpr float cos16f(int m) {
    m &= 31;
    if (m <= 8)  return  COS9(m);
    if (m <= 16) return -COS9(16 - m);
    if (m <= 24) return -COS9(m - 16);
    return COS9(32 - m);
}

struct Mat8 { float v[8][8]; };
struct Mat4 { float v[4][4]; };

__host__ __device__ constexpr Mat8 makeD() {
    Mat8 d{};
    for (int i = 0; i < 8; i++)
        for (int j = 0; j < 8; j++)
            d.v[i][j] = (i == 0 ? 0.35355339059327373f : 0.5f) * cos16f((2 * j + 1) * i);
    return d;
}

// Odd rows of D (i = 1,3,5,7), first 4 columns
__host__ __device__ constexpr Mat4 makeO() {
    Mat4 o{};
    constexpr Mat8 d = makeD();
    for (int k = 0; k < 4; k++)
        for (int j = 0; j < 4; j++)
            o.v[k][j] = d.v[2 * k + 1][j];
    return o;
}

// quality=50 -> scale=100 -> Q is exactly the integer luma table
__host__ __device__ constexpr Mat8 makeQ() {
    Mat8 q{};
    constexpr float t[8][8] = {
        {16, 11, 10, 16, 24, 40, 51, 61},
        {12, 12, 14, 19, 26, 58, 60, 55},
        {14, 13, 16, 24, 40, 57, 69, 56},
        {14, 17, 22, 29, 51, 87, 80, 62},
        {18, 22, 37, 56, 68, 109, 103, 77},
        {24, 35, 55, 64, 81, 104, 113, 92},
        {49, 64, 78, 87, 103, 121, 120, 101},
        {72, 92, 95, 98, 112, 100, 103, 99}};
    for (int i = 0; i < 8; i++)
        for (int j = 0; j < 8; j++)
            q.v[i][j] = t[i][j];
    return q;
}

__host__ __device__ constexpr Mat8 makeQinv() {
    Mat8 qi{};
    constexpr Mat8 q = makeQ();
    for (int i = 0; i < 8; i++)
        for (int j = 0; j < 8; j++)
            qi.v[i][j] = 1.0f / q.v[i][j];
    return qi;
}

constexpr int W         = 512;
constexpr int H         = 512;
constexpr int IMG_ELEMS = H * W;          // 262144
constexpr float RMAGIC  = 12582912.0f;    // 1.5 * 2^23 : round-half-even magic

constexpr float CC0 = 0.35355339059327373f; // 1/sqrt(8) (= 0.5*cos(pi/4))
constexpr float CC1 = 0.46193976625564337f; // 0.5*cos(pi/8)
constexpr float CC3 = 0.19134171618254492f; // 0.5*cos(3pi/8)

// Forward 8-pt DCT-II, output coefficient i scaled by qi (compile-time).
// out[i] = q_i * sum_j D[i][j] x[j].  36 FMA-pipe ops.
__device__ __forceinline__ void dct8_fwd_q(
    const float x[8], float out[8],
    float q0, float q1, float q2, float q3,
    float q4, float q5, float q6, float q7)
{
    constexpr Mat4 O = makeO();
    float s0 = x[0] + x[7], s1 = x[1] + x[6], s2 = x[2] + x[5], s3 = x[3] + x[4];
    float d0 = x[0] - x[7], d1 = x[1] - x[6], d2 = x[2] - x[5], d3 = x[3] - x[4];
    float ss0 = s0 + s3, ss1 = s1 + s2;
    float sd0 = s0 - s3, sd1 = s1 - s2;
    out[0] = (CC0 * q0) * ss0 + (CC0 * q0) * ss1;
    out[4] = (CC0 * q4) * ss0 - (CC0 * q4) * ss1;
    out[2] = (CC1 * q2) * sd0 + (CC3 * q2) * sd1;
    out[6] = (CC3 * q6) * sd0 - (CC1 * q6) * sd1;
    out[1] = (O.v[0][0]*q1)*d0 + (O.v[0][1]*q1)*d1 + (O.v[0][2]*q1)*d2 + (O.v[0][3]*q1)*d3;
    out[3] = (O.v[1][0]*q3)*d0 + (O.v[1][1]*q3)*d1 + (O.v[1][2]*q3)*d2 + (O.v[1][3]*q3)*d3;
    out[5] = (O.v[2][0]*q5)*d0 + (O.v[2][1]*q5)*d1 + (O.v[2][2]*q5)*d2 + (O.v[2][3]*q5)*d3;
    out[7] = (O.v[3][0]*q7)*d0 + (O.v[3][1]*q7)*d1 + (O.v[3][2]*q7)*d2 + (O.v[3][3]*q7)*d3;
}

// Inverse: out[j] = sum_i D[i][j] * (q_i * f[i]).  36 FMA-pipe ops.
__device__ __forceinline__ void dct8_inv_q(
    const float f[8], float out[8],
    float q0, float q1, float q2, float q3,
    float q4, float q5, float q6, float q7)
{
    constexpr Mat4 O = makeO();
    // even part: rows 0,4 symmetric across j<->3-j; rows 2,6 antisymmetric
    float a0 = (CC0 * q0) * f[0] + (CC0 * q4) * f[4];
    float a1 = (CC0 * q0) * f[0] - (CC0 * q4) * f[4];
    float b0 = (CC1 * q2) * f[2] + (CC3 * q6) * f[6];
    float b1 = (CC3 * q2) * f[2] - (CC1 * q6) * f[6];
    float e0 = a0 + b0, e1 = a1 + b1, e2 = a1 - b1, e3 = a0 - b0;
    // odd part: o_j = sum_k O[k][j] * q_{2k+1} * f[2k+1]
    float o0 = (O.v[0][0]*q1)*f[1] + (O.v[1][0]*q3)*f[3] + (O.v[2][0]*q5)*f[5] + (O.v[3][0]*q7)*f[7];
    float o1 = (O.v[0][1]*q1)*f[1] + (O.v[1][1]*q3)*f[3] + (O.v[2][1]*q5)*f[5] + (O.v[3][1]*q7)*f[7];
    float o2 = (O.v[0][2]*q1)*f[1] + (O.v[1][2]*q3)*f[3] + (O.v[2][2]*q5)*f[5] + (O.v[3][2]*q7)*f[7];
    float o3 = (O.v[0][3]*q1)*f[1] + (O.v[1][3]*q3)*f[3] + (O.v[2][3]*q5)*f[5] + (O.v[3][3]*q7)*f[7];
    out[0] = e0 + o0;  out[7] = e0 - o0;
    out[1] = e1 + o1;  out[6] = e1 - o1;
    out[2] = e2 + o2;  out[5] = e2 - o2;
    out[3] = e3 + o3;  out[4] = e3 - o3;
}

__global__ void __launch_bounds__(256, 4)
diffjpeg_kernel(const float* __restrict__ in, float* __restrict__ out, int nblocks) {
    constexpr Mat8 Q  = makeQ();
    constexpr Mat8 Qi = makeQinv();

    int t = blockIdx.x * 256 + threadIdx.x;
    if (t >= nblocks) return;

    int img = t >> 12;          // 4096 blocks per image
    int rem = t & 4095;
    int br  = rem >> 6;
    int bc  = rem & 63;

    size_t base = (size_t)img * IMG_ELEMS + (size_t)br * 8 * W + (size_t)bc * 8;
    const float* src = in + base;
    float* dst = out + base;

    float T[8][8];

    // ---- Phase 1: load + row transform (unscaled) ----
    #pragma unroll
    for (int r = 0; r < 8; r++) {
        const float* p = src + (size_t)r * W;
        float4 a = *reinterpret_cast<const float4*>(p);
        float4 b = *reinterpret_cast<const float4*>(p + 4);
        float x[8] = {a.x, a.y, a.z, a.w, b.x, b.y, b.z, b.w};
        dct8_fwd_q(x, T[r], 1.f, 1.f, 1.f, 1.f, 1.f, 1.f, 1.f, 1.f);
    }

    // ---- Phase 2: per column j: scaled col-DCT -> round -> scaled col-IDCT ----
    #pragma unroll
    for (int j = 0; j < 8; j++) {
        float col[8], f[8];
        #pragma unroll
        for (int r = 0; r < 8; r++) col[r] = T[r][j];
        // forward with 1/Q folded into coefficients: f[i] = (D X D^T)[i][j] / Q[i][j]
        dct8_fwd_q(col, f,
                   Qi.v[0][j], Qi.v[1][j], Qi.v[2][j], Qi.v[3][j],
                   Qi.v[4][j], Qi.v[5][j], Qi.v[6][j], Qi.v[7][j]);
        // round-half-even via magic constant (exact rintf semantics, |p| < 2^22)
        #pragma unroll
        for (int i = 0; i < 8; i++) {
            float r1 = __fadd_rn(f[i], RMAGIC);
            f[i] = __fadd_rn(r1, -RMAGIC);
        }
        // inverse with Q folded back in: col[r] = sum_i D[i][r] (f[i]*Q[i][j])
        dct8_inv_q(f, col,
                   Q.v[0][j], Q.v[1][j], Q.v[2][j], Q.v[3][j],
                   Q.v[4][j], Q.v[5][j], Q.v[6][j], Q.v[7][j]);
        #pragma unroll
        for (int r = 0; r < 8; r++) T[r][j] = col[r];
    }

    // ---- Phase 3: row inverse (unscaled) + store ----
    #pragma unroll
    for (int r = 0; r < 8; r++) {
        float y[8];
        dct8_inv_q(T[r], y, 1.f, 1.f, 1.f, 1.f, 1.f, 1.f, 1.f, 1.f);
        float* p = dst + (size_t)r * W;
        *reinterpret_cast<float4*>(p)     = make_float4(y[0], y[1], y[2], y[3]);
        *reinterpret_cast<float4*>(p + 4) = make_float4(y[4], y[5], y[6], y[7]);
    }
}

extern "C" void kernel_launch(void* const* d_in, const int* in_sizes, int n_in,
                              void* d_out, int out_size) {
    const float* in = (const float*)d_in[0];
    float* out = (float*)d_out;
    int nblocks = in_sizes[0] / 64;   // 393216
    int grid = (nblocks + 255) / 256;
    diffjpeg_kernel<<<grid, 256>>>(in, out, nblocks);
}

// round 7
// speedup vs baseline: 1.3000x; 1.3000x over previous
#include <cuda_runtime.h>
#include <cstddef>

// ---------------------------------------------------------------------------
// DiffJPEG: per 8x8 block  ->  D X D^T  ->  round(x/Q)*Q  ->  D^T X' D
// Input/Output: (32, 3, 512, 512) float32, contiguous.
//
// One thread per 8x8 block. Even/odd butterfly transforms (36 ops/8-pt),
// Q and 1/Q folded into phase-2 matvec immediates (constexpr products),
// magic-constant round-half-even.
// __launch_bounds__(256,3): R6 showed the ~80-reg working set SPILLS at a
// 64-reg cap (L1 61%, issue 37%); 3 CTAs/SM is this layout's occupancy
// ceiling, so give ptxas the 85-reg budget and keep zero spills.
// ---------------------------------------------------------------------------

__host__ __device__ constexpr float COS9(int m) {
    constexpr float t[9] = {
        1.0f,
        0.9807852804032304f,
        0.9238795325112868f,
        0.8314696123025452f,
        0.7071067811865476f,
        0.5555702330196022f,
        0.3826834323650898f,
        0.1950903220161283f,
        0.0f
    };
    return t[m];
}

__host__ __device__ constexpr float cos16f(int m) {
    m &= 31;
    if (m <= 8)  return  COS9(m);
    if (m <= 16) return -COS9(16 - m);
    if (m <= 24) return -COS9(m - 16);
    return COS9(32 - m);
}

struct Mat8 { float v[8][8]; };
struct Mat4 { float v[4][4]; };

__host__ __device__ constexpr Mat8 makeD() {
    Mat8 d{};
    for (int i = 0; i < 8; i++)
        for (int j = 0; j < 8; j++)
            d.v[i][j] = (i == 0 ? 0.35355339059327373f : 0.5f) * cos16f((2 * j + 1) * i);
    return d;
}

// Odd rows of D (i = 1,3,5,7), first 4 columns
__host__ __device__ constexpr Mat4 makeO() {
    Mat4 o{};
    constexpr Mat8 d = makeD();
    for (int k = 0; k < 4; k++)
        for (int j = 0; j < 4; j++)
            o.v[k][j] = d.v[2 * k + 1][j];
    return o;
}

// quality=50 -> scale=100 -> Q is exactly the integer luma table
__host__ __device__ constexpr Mat8 makeQ() {
    Mat8 q{};
    constexpr float t[8][8] = {
        {16, 11, 10, 16, 24, 40, 51, 61},
        {12, 12, 14, 19, 26, 58, 60, 55},
        {14, 13, 16, 24, 40, 57, 69, 56},
        {14, 17, 22, 29, 51, 87, 80, 62},
        {18, 22, 37, 56, 68, 109, 103, 77},
        {24, 35, 55, 64, 81, 104, 113, 92},
        {49, 64, 78, 87, 103, 121, 120, 101},
        {72, 92, 95, 98, 112, 100, 103, 99}};
    for (int i = 0; i < 8; i++)
        for (int j = 0; j < 8; j++)
            q.v[i][j] = t[i][j];
    return q;
}

__host__ __device__ constexpr Mat8 makeQinv() {
    Mat8 qi{};
    constexpr Mat8 q = makeQ();
    for (int i = 0; i < 8; i++)
        for (int j = 0; j < 8; j++)
            qi.v[i][j] = 1.0f / q.v[i][j];
    return qi;
}

constexpr int W         = 512;
constexpr int H         = 512;
constexpr int IMG_ELEMS = H * W;          // 262144
constexpr float RMAGIC  = 12582912.0f;    // 1.5 * 2^23 : round-half-even magic

constexpr float CC0 = 0.35355339059327373f; // 1/sqrt(8) (= 0.5*cos(pi/4))
constexpr float CC1 = 0.46193976625564337f; // 0.5*cos(pi/8)
constexpr float CC3 = 0.19134171618254492f; // 0.5*cos(3pi/8)

// Forward 8-pt DCT-II, output coefficient i scaled by qi (compile-time).
// out[i] = q_i * sum_j D[i][j] x[j].  36 FMA-pipe ops.
__device__ __forceinline__ void dct8_fwd_q(
    const float x[8], float out[8],
    float q0, float q1, float q2, float q3,
    float q4, float q5, float q6, float q7)
{
    constexpr Mat4 O = makeO();
    float s0 = x[0] + x[7], s1 = x[1] + x[6], s2 = x[2] + x[5], s3 = x[3] + x[4];
    float d0 = x[0] - x[7], d1 = x[1] - x[6], d2 = x[2] - x[5], d3 = x[3] - x[4];
    float ss0 = s0 + s3, ss1 = s1 + s2;
    float sd0 = s0 - s3, sd1 = s1 - s2;
    out[0] = (CC0 * q0) * ss0 + (CC0 * q0) * ss1;
    out[4] = (CC0 * q4) * ss0 - (CC0 * q4) * ss1;
    out[2] = (CC1 * q2) * sd0 + (CC3 * q2) * sd1;
    out[6] = (CC3 * q6) * sd0 - (CC1 * q6) * sd1;
    out[1] = (O.v[0][0]*q1)*d0 + (O.v[0][1]*q1)*d1 + (O.v[0][2]*q1)*d2 + (O.v[0][3]*q1)*d3;
    out[3] = (O.v[1][0]*q3)*d0 + (O.v[1][1]*q3)*d1 + (O.v[1][2]*q3)*d2 + (O.v[1][3]*q3)*d3;
    out[5] = (O.v[2][0]*q5)*d0 + (O.v[2][1]*q5)*d1 + (O.v[2][2]*q5)*d2 + (O.v[2][3]*q5)*d3;
    out[7] = (O.v[3][0]*q7)*d0 + (O.v[3][1]*q7)*d1 + (O.v[3][2]*q7)*d2 + (O.v[3][3]*q7)*d3;
}

// Inverse: out[j] = sum_i D[i][j] * (q_i * f[i]).  36 FMA-pipe ops.
__device__ __forceinline__ void dct8_inv_q(
    const float f[8], float out[8],
    float q0, float q1, float q2, float q3,
    float q4, float q5, float q6, float q7)
{
    constexpr Mat4 O = makeO();
    // even part: rows 0,4 symmetric across j<->3-j; rows 2,6 antisymmetric
    float a0 = (CC0 * q0) * f[0] + (CC0 * q4) * f[4];
    float a1 = (CC0 * q0) * f[0] - (CC0 * q4) * f[4];
    float b0 = (CC1 * q2) * f[2] + (CC3 * q6) * f[6];
    float b1 = (CC3 * q2) * f[2] - (CC1 * q6) * f[6];
    float e0 = a0 + b0, e1 = a1 + b1, e2 = a1 - b1, e3 = a0 - b0;
    // odd part: o_j = sum_k O[k][j] * q_{2k+1} * f[2k+1]
    float o0 = (O.v[0][0]*q1)*f[1] + (O.v[1][0]*q3)*f[3] + (O.v[2][0]*q5)*f[5] + (O.v[3][0]*q7)*f[7];
    float o1 = (O.v[0][1]*q1)*f[1] + (O.v[1][1]*q3)*f[3] + (O.v[2][1]*q5)*f[5] + (O.v[3][1]*q7)*f[7];
    float o2 = (O.v[0][2]*q1)*f[1] + (O.v[1][2]*q3)*f[3] + (O.v[2][2]*q5)*f[5] + (O.v[3][2]*q7)*f[7];
    float o3 = (O.v[0][3]*q1)*f[1] + (O.v[1][3]*q3)*f[3] + (O.v[2][3]*q5)*f[5] + (O.v[3][3]*q7)*f[7];
    out[0] = e0 + o0;  out[7] = e0 - o0;
    out[1] = e1 + o1;  out[6] = e1 - o1;
    out[2] = e2 + o2;  out[5] = e2 - o2;
    out[3] = e3 + o3;  out[4] = e3 - o3;
}

__global__ void __launch_bounds__(256, 3)
diffjpeg_kernel(const float* __restrict__ in, float* __restrict__ out, int nblocks) {
    constexpr Mat8 Q  = makeQ();
    constexpr Mat8 Qi = makeQinv();

    int t = blockIdx.x * 256 + threadIdx.x;
    if (t >= nblocks) return;

    int img = t >> 12;          // 4096 blocks per image
    int rem = t & 4095;
    int br  = rem >> 6;
    int bc  = rem & 63;

    size_t base = (size_t)img * IMG_ELEMS + (size_t)br * 8 * W + (size_t)bc * 8;
    const float* src = in + base;
    float* dst = out + base;

    float T[8][8];

    // ---- Phase 1: load + row transform (unscaled) ----
    #pragma unroll
    for (int r = 0; r < 8; r++) {
        const float* p = src + (size_t)r * W;
        float4 a = *reinterpret_cast<const float4*>(p);
        float4 b = *reinterpret_cast<const float4*>(p + 4);
        float x[8] = {a.x, a.y, a.z, a.w, b.x, b.y, b.z, b.w};
        dct8_fwd_q(x, T[r], 1.f, 1.f, 1.f, 1.f, 1.f, 1.f, 1.f, 1.f);
    }

    // ---- Phase 2: per column j: scaled col-DCT -> round -> scaled col-IDCT ----
    #pragma unroll
    for (int j = 0; j < 8; j++) {
        float col[8], f[8];
        #pragma unroll
        for (int r = 0; r < 8; r++) col[r] = T[r][j];
        // forward with 1/Q folded into coefficients: f[i] = (D X D^T)[i][j] / Q[i][j]
        dct8_fwd_q(col, f,
                   Qi.v[0][j], Qi.v[1][j], Qi.v[2][j], Qi.v[3][j],
                   Qi.v[4][j], Qi.v[5][j], Qi.v[6][j], Qi.v[7][j]);
        // round-half-even via magic constant (exact rintf semantics, |p| < 2^22)
        #pragma unroll
        for (int i = 0; i < 8; i++) {
            float r1 = __fadd_rn(f[i], RMAGIC);
            f[i] = __fadd_rn(r1, -RMAGIC);
        }
        // inverse with Q folded back in: col[r] = sum_i D[i][r] (f[i]*Q[i][j])
        dct8_inv_q(f, col,
                   Q.v[0][j], Q.v[1][j], Q.v[2][j], Q.v[3][j],
                   Q.v[4][j], Q.v[5][j], Q.v[6][j], Q.v[7][j]);
        #pragma unroll
        for (int r = 0; r < 8; r++) T[r][j] = col[r];
    }

    // ---- Phase 3: row inverse (unscaled) + store ----
    #pragma unroll
    for (int r = 0; r < 8; r++) {
        float y[8];
        dct8_inv_q(T[r], y, 1.f, 1.f, 1.f, 1.f, 1.f, 1.f, 1.f, 1.f);
        float* p = dst + (size_t)r * W;
        *reinterpret_cast<float4*>(p)     = make_float4(y[0], y[1], y[2], y[3]);
        *reinterpret_cast<float4*>(p + 4) = make_float4(y[4], y[5], y[6], y[7]);
    }
}

extern "C" void kernel_launch(void* const* d_in, const int* in_sizes, int n_in,
                              void* d_out, int out_size) {
    const float* in = (const float*)d_in[0];
    float* out = (float*)d_out;
    int nblocks = in_sizes[0] / 64;   // 393216
    int grid = (nblocks + 255) / 256;
    diffjpeg_kernel<<<grid, 256>>>(in, out, nblocks);
}

// round 8
// speedup vs baseline: 1.3775x; 1.0596x over previous
#include <cuda_runtime.h>
#include <cstddef>

// ---------------------------------------------------------------------------
// DiffJPEG: per 8x8 block  ->  D X D^T  ->  round(x/Q)*Q  ->  D^T X' D
// Input/Output: (32, 3, 512, 512) float32, contiguous.
//
// One thread per 8x8 block, __launch_bounds__(256,3) (proven spill-free).
// R3's flat 4x4 E/O matvec shape (best-scheduling encoding measured across
// R3/R6/R7), with:
//  - 1/Q and Q folded into phase-2 matvec immediates (same shape, new consts)
//  - explicit 2-wave load hoisting (8 outstanding LDG.128 per wave)
//  - streaming cache hints (data touched exactly once)
// ---------------------------------------------------------------------------

__host__ __device__ constexpr float COS9(int m) {
    constexpr float t[9] = {
        1.0f,
        0.9807852804032304f,
        0.9238795325112868f,
        0.8314696123025452f,
        0.7071067811865476f,
        0.5555702330196022f,
        0.3826834323650898f,
        0.1950903220161283f,
        0.0f
    };
    return t[m];
}

__host__ __device__ constexpr float cos16f(int m) {
    m &= 31;
    if (m <= 8)  return  COS9(m);
    if (m <= 16) return -COS9(16 - m);
    if (m <= 24) return -COS9(m - 16);
    return COS9(32 - m);
}

struct Mat8 { float v[8][8]; };
struct Mat4 { float v[4][4]; };

__host__ __device__ constexpr Mat8 makeD() {
    Mat8 d{};
    for (int i = 0; i < 8; i++)
        for (int j = 0; j < 8; j++)
            d.v[i][j] = (i == 0 ? 0.35355339059327373f : 0.5f) * cos16f((2 * j + 1) * i);
    return d;
}

// Even rows of D (i = 0,2,4,6), first 4 columns
__host__ __device__ constexpr Mat4 makeE() {
    Mat4 e{};
    constexpr Mat8 d = makeD();
    for (int k = 0; k < 4; k++)
        for (int j = 0; j < 4; j++)
            e.v[k][j] = d.v[2 * k][j];
    return e;
}
// Odd rows of D (i = 1,3,5,7), first 4 columns
__host__ __device__ constexpr Mat4 makeO() {
    Mat4 o{};
    constexpr Mat8 d = makeD();
    for (int k = 0; k < 4; k++)
        for (int j = 0; j < 4; j++)
            o.v[k][j] = d.v[2 * k + 1][j];
    return o;
}

// quality=50 -> scale=100 -> Q is exactly the integer luma table
__host__ __device__ constexpr Mat8 makeQ() {
    Mat8 q{};
    constexpr float t[8][8] = {
        {16, 11, 10, 16, 24, 40, 51, 61},
        {12, 12, 14, 19, 26, 58, 60, 55},
        {14, 13, 16, 24, 40, 57, 69, 56},
        {14, 17, 22, 29, 51, 87, 80, 62},
        {18, 22, 37, 56, 68, 109, 103, 77},
        {24, 35, 55, 64, 81, 104, 113, 92},
        {49, 64, 78, 87, 103, 121, 120, 101},
        {72, 92, 95, 98, 112, 100, 103, 99}};
    for (int i = 0; i < 8; i++)
        for (int j = 0; j < 8; j++)
            q.v[i][j] = t[i][j];
    return q;
}

__host__ __device__ constexpr Mat8 makeQinv() {
    Mat8 qi{};
    constexpr Mat8 q = makeQ();
    for (int i = 0; i < 8; i++)
        for (int j = 0; j < 8; j++)
            qi.v[i][j] = 1.0f / q.v[i][j];
    return qi;
}

constexpr int W         = 512;
constexpr int H         = 512;
constexpr int IMG_ELEMS = H * W;          // 262144
constexpr float RMAGIC  = 12582912.0f;    // 1.5 * 2^23 : round-half-even magic

// Forward 8-pt DCT-II (R3 matvec shape), output i scaled by q_i (all q's are
// compile-time literals at every call site -> immediates after folding).
// out[i] = q_i * sum_j D[i][j] x[j]
__device__ __forceinline__ void dct8_fwd_q(
    const float x[8], float out[8],
    float q0, float q1, float q2, float q3,
    float q4, float q5, float q6, float q7)
{
    constexpr Mat4 E = makeE();
    constexpr Mat4 O = makeO();
    const float qe[4] = {q0, q2, q4, q6};
    const float qo[4] = {q1, q3, q5, q7};
    float s[4], d[4];
    #pragma unroll
    for (int j = 0; j < 4; j++) {
        s[j] = x[j] + x[7 - j];
        d[j] = x[j] - x[7 - j];
    }
    #pragma unroll
    for (int k = 0; k < 4; k++) {
        float se = s[0] * (E.v[k][0] * qe[k]);
        float so = d[0] * (O.v[k][0] * qo[k]);
        #pragma unroll
        for (int j = 1; j < 4; j++) {
            se += s[j] * (E.v[k][j] * qe[k]);
            so += d[j] * (O.v[k][j] * qo[k]);
        }
        out[2 * k]     = se;
        out[2 * k + 1] = so;
    }
}

// Inverse (R3 matvec shape): out[j] = sum_i D[i][j] * (q_i * f[i])
__device__ __forceinline__ void dct8_inv_q(
    const float f[8], float out[8],
    float q0, float q1, float q2, float q3,
    float q4, float q5, float q6, float q7)
{
    constexpr Mat4 E = makeE();
    constexpr Mat4 O = makeO();
    const float qe[4] = {q0, q2, q4, q6};
    const float qo[4] = {q1, q3, q5, q7};
    #pragma unroll
    for (int j = 0; j < 4; j++) {
        float e = f[0] * (E.v[0][j] * qe[0]);
        float o = f[1] * (O.v[0][j] * qo[0]);
        #pragma unroll
        for (int k = 1; k < 4; k++) {
            e += f[2 * k]     * (E.v[k][j] * qe[k]);
            o += f[2 * k + 1] * (O.v[k][j] * qo[k]);
        }
        out[j]     = e + o;
        out[7 - j] = e - o;
    }
}

__global__ void __launch_bounds__(256, 3)
diffjpeg_kernel(const float* __restrict__ in, float* __restrict__ out, int nblocks) {
    constexpr Mat8 Q  = makeQ();
    constexpr Mat8 Qi = makeQinv();

    int t = blockIdx.x * 256 + threadIdx.x;
    if (t >= nblocks) return;

    int img = t >> 12;          // 4096 blocks per image
    int rem = t & 4095;
    int br  = rem >> 6;
    int bc  = rem & 63;

    size_t base = (size_t)img * IMG_ELEMS + (size_t)br * 8 * W + (size_t)bc * 8;
    const float* src = in + base;
    float* dst = out + base;

    float T[8][8];

    // ---- Phase 1: two waves of 4 rows; loads hoisted ahead of compute ----
    #pragma unroll
    for (int w = 0; w < 2; w++) {
        float4 a[4], b[4];
        #pragma unroll
        for (int r = 0; r < 4; r++) {
            const float* p = src + (size_t)(w * 4 + r) * W;
            a[r] = __ldcs(reinterpret_cast<const float4*>(p));
            b[r] = __ldcs(reinterpret_cast<const float4*>(p + 4));
        }
        #pragma unroll
        for (int r = 0; r < 4; r++) {
            float x[8] = {a[r].x, a[r].y, a[r].z, a[r].w,
                          b[r].x, b[r].y, b[r].z, b[r].w};
            dct8_fwd_q(x, T[w * 4 + r], 1.f, 1.f, 1.f, 1.f, 1.f, 1.f, 1.f, 1.f);
        }
    }

    // ---- Phase 2: per column j: (D·)/Q -> round -> (D^T·)*Q ----
    #pragma unroll
    for (int j = 0; j < 8; j++) {
        float col[8], f[8];
        #pragma unroll
        for (int r = 0; r < 8; r++) col[r] = T[r][j];
        dct8_fwd_q(col, f,
                   Qi.v[0][j], Qi.v[1][j], Qi.v[2][j], Qi.v[3][j],
                   Qi.v[4][j], Qi.v[5][j], Qi.v[6][j], Qi.v[7][j]);
        // round-half-even via magic constant (exact rintf semantics, |p| < 2^22)
        #pragma unroll
        for (int i = 0; i < 8; i++) {
            float r1 = __fadd_rn(f[i], RMAGIC);
            f[i] = __fadd_rn(r1, -RMAGIC);
        }
        dct8_inv_q(f, col,
                   Q.v[0][j], Q.v[1][j], Q.v[2][j], Q.v[3][j],
                   Q.v[4][j], Q.v[5][j], Q.v[6][j], Q.v[7][j]);
        #pragma unroll
        for (int r = 0; r < 8; r++) T[r][j] = col[r];
    }

    // ---- Phase 3: row inverse + streaming store ----
    #pragma unroll
    for (int r = 0; r < 8; r++) {
        float y[8];
        dct8_inv_q(T[r], y, 1.f, 1.f, 1.f, 1.f, 1.f, 1.f, 1.f, 1.f);
        float* p = dst + (size_t)r * W;
        __stcs(reinterpret_cast<float4*>(p),     make_float4(y[0], y[1], y[2], y[3]));
        __stcs(reinterpret_cast<float4*>(p + 4), make_float4(y[4], y[5], y[6], y[7]));
    }
}

extern "C" void kernel_launch(void* const* d_in, const int* in_sizes, int n_in,
                              void* d_out, int out_size) {
    const float* in = (const float*)d_in[0];
    float* out = (float*)d_out;
    int nblocks = in_sizes[0] / 64;   // 393216
    int grid = (nblocks + 255) / 256;
    diffjpeg_kernel<<<grid, 256>>>(in, out, nblocks);
}